// round 13
// baseline (speedup 1.0000x reference)
#include <cuda_runtime.h>
#include <math.h>

#define NN   64
#define KK   32
#define FF   1024
#define OO   64
#define JJ   33
#define C2c  32
#define NCLS 10
#define BN_EPS 1e-5f

typedef unsigned long long ull;
typedef unsigned int uint;

// ---------------- scratch ----------------
__device__ float g_C[NN * JJ * FF];
__device__ float g_part[8 * NN * JJ * OO];
__device__ float g_O1[NN * JJ * OO];
__device__ float g_Xrow[NN * OO];
__device__ float g_X2[NN * C2c];
__device__ float g_s[NN * FF];               // neighbor sums
__device__ uint  g_aux[NN * FF];             // packed: ip(10) | m(11)<<10 | neg<<21
__device__ int   g_cnt[64];
__device__ int   g_cnt2[1];

__device__ __forceinline__ ull pk2(float lo, float hi) {
    ull r; asm("mov.b64 %0, {%1, %2};" : "=l"(r) : "f"(lo), "f"(hi)); return r;
}
__device__ __forceinline__ void upk2(ull v, float& lo, float& hi) {
    asm("mov.b64 {%0, %1}, %2;" : "=f"(lo), "=f"(hi) : "l"(v));
}
__device__ __forceinline__ ull ffma2(ull a, ull b, ull c) {
    ull d; asm("fma.rn.f32x2 %0, %1, %2, %3;" : "=l"(d) : "l"(a), "l"(b), "l"(c)); return d;
}

// ============================================================================
// K0: full-chip neighbor sum. grid=(4,64), block=256.
// Same k-ascending order as before -> bit-identical keys.
// ============================================================================
__global__ void k_pre(const float* __restrict__ nb)
{
    int n = blockIdx.y;
    int f = blockIdx.x * 256 + threadIdx.x;
    const float* nbb = nb + (size_t)n * KK * FF + f;
    float s = 0.f;
    #pragma unroll
    for (int k = 0; k < KK; k++) s += nbb[k * FF];
    g_s[n * FF + f] = s;
}

// ============================================================================
// K1: per-node hybrid bitonic sort (payload, float2 smem, double-buffered:
// ONE barrier per cross-warp pass). grid=64, block=1024.
// ============================================================================
__global__ void k_sort(const float* __restrict__ x)
{
    int n = blockIdx.x, t = threadIdx.x;
    __shared__ float2 buf[2][FF];            // 16 KB

    if (n == 0 && t < 64) g_cnt[t] = 0;
    if (n == 0 && t == 64) g_cnt2[0] = 0;

    float xv = x[(size_t)n * FF + t];
    float s  = g_s[(size_t)n * FF + t];

    float key = s / xv;
    int   pay = t;
    float myr = key;

    #pragma unroll
    for (int k = 2; k <= 32; k <<= 1) {
        #pragma unroll
        for (int j = k >> 1; j >= 1; j >>= 1) {
            float ok = __shfl_xor_sync(0xffffffffu, key, j);
            int   op = __shfl_xor_sync(0xffffffffu, pay, j);
            bool keepmin = (((t & k) == 0) == ((t & j) == 0));
            bool take = keepmin ? (ok < key) : (ok > key);
            if (take) { key = ok; pay = op; }
        }
    }
    int c = 0;
    for (int k = 64; k <= FF; k <<= 1) {
        for (int j = k >> 1; j >= 32; j >>= 1) {
            buf[c][t] = make_float2(key, __int_as_float(pay));
            __syncthreads();
            float2 o = buf[c][t ^ j];
            bool keepmin = (((t & k) == 0) == ((t & j) == 0));
            bool take = keepmin ? (o.x < key) : (o.x > key);
            if (take) { key = o.x; pay = __float_as_int(o.y); }
            c ^= 1;
        }
        #pragma unroll
        for (int j = 16; j >= 1; j >>= 1) {
            float ok = __shfl_xor_sync(0xffffffffu, key, j);
            int   op = __shfl_xor_sync(0xffffffffu, pay, j);
            bool keepmin = (((t & k) == 0) == ((t & j) == 0));
            bool take = keepmin ? (ok < key) : (ok > key);
            if (take) { key = ok; pay = op; }
        }
    }

    __syncthreads();
    float* sk  = (float*)&buf[0][0];
    int*   ipA = (int*)&buf[1][0];
    sk[t] = key;
    ipA[pay] = t;
    __syncthreads();

    float th = -myr;
    int lo = 0, hi = FF;
    #pragma unroll
    for (int it = 0; it < 10; it++) {
        int mid = (lo + hi) >> 1;
        if (sk[mid] < th) lo = mid + 1; else hi = mid;
    }
    uint pk = (uint)ipA[t] | ((uint)lo << 10) | ((xv >= 0.f) ? 0u : (1u << 21));
    g_aux[(size_t)n * FF + t] = pk;
}

// ============================================================================
// K2: batched 3-column scan. grid=(11,64), block=1024.  (R10-proven)
// ============================================================================
__global__ void k_cols(const float* __restrict__ x, const float* __restrict__ nb)
{
    int n = blockIdx.y, t = threadIdx.x;
    int j0 = blockIdx.x * 3;
    __shared__ float sc[3][FF];
    __shared__ float ws[3][32];

    uint  pk = g_aux[(size_t)n * FF + t];
    int   ip = pk & 1023;
    int   m  = (pk >> 10) & 2047;
    float sg = (pk & (1u << 21)) ? -1.f : 1.f;

    float v[3];
    #pragma unroll
    for (int u = 0; u < 3; u++) {
        int j = j0 + u;
        const float* col = (j == 0) ? (x + (size_t)n * FF)
                                    : (nb + ((size_t)n * KK + (j - 1)) * FF);
        v[u] = col[t] * sg;
    }
    #pragma unroll
    for (int u = 0; u < 3; u++) sc[u][ip] = v[u];
    __syncthreads();

    float val[3];
    #pragma unroll
    for (int u = 0; u < 3; u++) val[u] = sc[u][t];

    int lane = t & 31, wid = t >> 5;
    #pragma unroll
    for (int d = 1; d < 32; d <<= 1) {
        #pragma unroll
        for (int u = 0; u < 3; u++) {
            float o = __shfl_up_sync(0xffffffffu, val[u], d);
            if (lane >= d) val[u] += o;
        }
    }
    if (lane == 31) {
        #pragma unroll
        for (int u = 0; u < 3; u++) ws[u][wid] = val[u];
    }
    __syncthreads();
    if (wid == 0) {
        float wv[3];
        #pragma unroll
        for (int u = 0; u < 3; u++) wv[u] = ws[u][lane];
        #pragma unroll
        for (int d = 1; d < 32; d <<= 1) {
            #pragma unroll
            for (int u = 0; u < 3; u++) {
                float o = __shfl_up_sync(0xffffffffu, wv[u], d);
                if (lane >= d) wv[u] += o;
            }
        }
        #pragma unroll
        for (int u = 0; u < 3; u++) ws[u][lane] = wv[u];
    }
    __syncthreads();
    #pragma unroll
    for (int u = 0; u < 3; u++) {
        float off = wid ? ws[u][wid - 1] : 0.f;
        sc[u][t] = val[u] + off;
    }
    __syncthreads();

    #pragma unroll
    for (int u = 0; u < 3; u++) {
        float T = sc[u][FF - 1];
        float P = m ? sc[u][m - 1] : 0.f;
        g_C[((size_t)n * JJ + j0 + u) * FF + t] = sg * (T - 2.f * P);
    }
}

// ============================================================================
// K3: GEMM (split-K 8, FFMA2, DOUBLE-BUFFERED staging) + fused reduce.
// grid=(33,8), block=256.  (R12-proven)
// ============================================================================
__global__ void __launch_bounds__(256) k_gemm(const float* __restrict__ W1)
{
    __shared__ float Cs[2][32 * 68];
    __shared__ float Wt[2][32 * 68];
    __shared__ int last;
    int mt  = blockIdx.x;
    int ks  = blockIdx.y;
    int tid = threadIdx.x;
    int mg  = tid >> 4;
    int og  = tid & 15;

    ull acc01[4], acc23[4];
    #pragma unroll
    for (int i = 0; i < 4; i++) { acc01[i] = pk2(0.f, 0.f); acc23[i] = acc01[i]; }

    int kb0 = ks * (FF / 8);
    int row0 = tid >> 5;
    int kcs  = tid & 31;

    float cv[8], wv[8];
    #pragma unroll
    for (int u = 0; u < 8; u++) {
        int r = row0 + u * 8;
        cv[u] = g_C[(size_t)(mt * 64 + r) * FF + kb0 + kcs];
        wv[u] = W1[(size_t)r * FF + kb0 + kcs];
    }
    #pragma unroll
    for (int u = 0; u < 8; u++) {
        int r = row0 + u * 8;
        Cs[0][kcs * 68 + r] = cv[u];
        Wt[0][kcs * 68 + r] = wv[u];
    }
    __syncthreads();

    int cb = 0;
    #pragma unroll
    for (int blk = 0; blk < 4; blk++) {
        if (blk < 3) {
            int kb = kb0 + (blk + 1) * 32;
            #pragma unroll
            for (int u = 0; u < 8; u++) {
                int r = row0 + u * 8;
                cv[u] = g_C[(size_t)(mt * 64 + r) * FF + kb + kcs];
                wv[u] = W1[(size_t)r * FF + kb + kcs];
            }
        }
        #pragma unroll
        for (int kc = 0; kc < 32; kc++) {
            float4 cvv = *(const float4*)&Cs[cb][kc * 68 + mg * 4];
            ulonglong2 wvv = *(const ulonglong2*)&Wt[cb][kc * 68 + og * 4];
            ull cp;
            cp = pk2(cvv.x, cvv.x);
            acc01[0] = ffma2(cp, wvv.x, acc01[0]); acc23[0] = ffma2(cp, wvv.y, acc23[0]);
            cp = pk2(cvv.y, cvv.y);
            acc01[1] = ffma2(cp, wvv.x, acc01[1]); acc23[1] = ffma2(cp, wvv.y, acc23[1]);
            cp = pk2(cvv.z, cvv.z);
            acc01[2] = ffma2(cp, wvv.x, acc01[2]); acc23[2] = ffma2(cp, wvv.y, acc23[2]);
            cp = pk2(cvv.w, cvv.w);
            acc01[3] = ffma2(cp, wvv.x, acc01[3]); acc23[3] = ffma2(cp, wvv.y, acc23[3]);
        }
        if (blk < 3) {
            #pragma unroll
            for (int u = 0; u < 8; u++) {
                int r = row0 + u * 8;
                Cs[cb ^ 1][kcs * 68 + r] = cv[u];
                Wt[cb ^ 1][kcs * 68 + r] = wv[u];
            }
        }
        __syncthreads();
        cb ^= 1;
    }

    float* pb = g_part + (size_t)ks * (NN * JJ * OO) + (size_t)mt * 64 * OO;
    #pragma unroll
    for (int i = 0; i < 4; i++) {
        float4 r;
        upk2(acc01[i], r.x, r.y);
        upk2(acc23[i], r.z, r.w);
        *(float4*)&pb[(mg * 4 + i) * OO + og * 4] = r;
    }

    __threadfence();
    __syncthreads();
    if (tid == 0) last = (atomicAdd(&g_cnt[mt], 1) == 7);
    __syncthreads();
    if (last) {
        __threadfence();
        const float4* ps = (const float4*)g_part;
        float4* po = (float4*)g_O1;
        float4* px = (float4*)g_Xrow;
        for (int i = tid; i < 1024; i += 256) {
            float4 a = make_float4(0.f, 0.f, 0.f, 0.f);
            #pragma unroll
            for (int s = 0; s < 8; s++) {
                float4 p = ps[(size_t)s * (NN * JJ * OO / 4) + mt * 1024 + i];
                a.x += p.x; a.y += p.y; a.z += p.z; a.w += p.w;
            }
            po[mt * 1024 + i] = a;
            int m = mt * 64 + (i >> 4);
            if (m % 33 == 0) px[(m / 33) * 16 + (i & 15)] = a;
        }
    }
}

// ============================================================================
// K4: layer2 + fused final. grid=64, block=256.  (R10-proven version)
// ============================================================================
__global__ void k_layer2(const float* __restrict__ W2,
                         const float* __restrict__ bn1w, const float* __restrict__ bn1b,
                         const float* __restrict__ bn2w, const float* __restrict__ bn2b,
                         const float* __restrict__ lw,  const float* __restrict__ lb,
                         float* __restrict__ out)
{
    int n = blockIdx.x, t = threadIdx.x;
    __shared__ float nbs[KK * 64];
    __shared__ float red[1024];
    __shared__ float tmp[16];
    __shared__ float x1s[64], t2s[64], xa2s[64];
    __shared__ float gm[4], gr[4], cm[4], cr[4];
    __shared__ int last;

    const float4* O1v = (const float4*)g_O1;
    const float4* Xv  = (const float4*)g_Xrow;
    float4* nbsv = (float4*)nbs;

    #pragma unroll
    for (int u = 0; u < 2; u++) {
        int i4 = u * 256 + t;
        int row = i4 >> 4, c4 = i4 & 15;
        nbsv[i4] = O1v[((size_t)(n * JJ + 1 + row)) * 16 + c4];
    }

    int ch = (t & 15) >> 2;
    float gs1 = 0.f, gs2 = 0.f;
    #pragma unroll
    for (int u = 0; u < 4; u++) {
        float4 q = Xv[u * 256 + t];
        gs1 += q.x + q.y + q.z + q.w;
        gs2 += q.x * q.x + q.y * q.y + q.z * q.z + q.w * q.w;
    }
    __syncthreads();

    float ns1 = 0.f, ns2 = 0.f;
    #pragma unroll
    for (int u = 0; u < 2; u++) {
        float4 q = nbsv[u * 256 + t];
        ns1 += q.x + q.y + q.z + q.w;
        ns2 += q.x * q.x + q.y * q.y + q.z * q.z + q.w * q.w;
    }
    int sic = ((t >> 4) << 2) | (t & 3);
    red[      ch * 64 + sic] = gs1;
    red[256 + ch * 64 + sic] = gs2;
    red[512 + ch * 64 + sic] = ns1;
    red[768 + ch * 64 + sic] = ns2;
    __syncthreads();

    {
        int arr = t >> 6, c = (t >> 4) & 3, l = t & 15;
        int base = arr * 256 + c * 64;
        float v = red[base + l] + red[base + l + 16] + red[base + l + 32] + red[base + l + 48];
        #pragma unroll
        for (int d = 8; d > 0; d >>= 1)
            v += __shfl_down_sync(0xffffffffu, v, d, 16);
        if (l == 0) tmp[arr * 4 + c] = v;
    }
    __syncthreads();
    if (t < 4) {
        float m = tmp[t] / 1024.f;
        gm[t] = m; gr[t] = rsqrtf(tmp[4 + t] / 1024.f - m * m + BN_EPS);
        float m2 = tmp[8 + t] / 512.f;
        cm[t] = m2; cr[t] = rsqrtf(tmp[12 + t] / 512.f - m2 * m2 + BN_EPS);
    }
    __syncthreads();

    if (t < 64) {
        float v = g_Xrow[n * OO + t];
        int c = t >> 4;
        float y = (v - gm[c]) * gr[c] * bn1w[c] + bn1b[c];
        x1s[t] = y / (1.f + fabsf(y));
    }
    #pragma unroll
    for (int u = 0; u < 2; u++) {
        int i4 = u * 256 + t;
        int c = ((i4 & 15) >> 2);
        float4 q = nbsv[i4];
        float sw = cr[c] * bn1w[c];
        float y;
        y = (q.x - cm[c]) * sw + bn1b[c]; q.x = y / (1.f + fabsf(y));
        y = (q.y - cm[c]) * sw + bn1b[c]; q.y = y / (1.f + fabsf(y));
        y = (q.z - cm[c]) * sw + bn1b[c]; q.z = y / (1.f + fabsf(y));
        y = (q.w - cm[c]) * sw + bn1b[c]; q.w = y / (1.f + fabsf(y));
        nbsv[i4] = q;
    }
    __syncthreads();
    if (t < 64) {
        float a = 0.f;
        #pragma unroll
        for (int k = 0; k < KK; k++) a += nbs[k * 64 + t];
        t2s[t] = a;
    }
    __syncthreads();

    {
        int ai = t >> 4, b = t & 15;
        float sgv[4], ctr[4];
        float den = 1e-7f;
        #pragma unroll
        for (int cc = 0; cc < 4; cc++) {
            float raw = x1s[cc * 16 + ai] * t2s[cc * 16 + b]
                      + x1s[cc * 16 + b]  * t2s[cc * 16 + ai];
            float mag = sqrtf(fmaxf(fabsf(raw), 1e-8f));
            float sg  = (raw > 0.f) ? mag : ((raw < 0.f) ? -mag : 0.f);
            sgv[cc] = sg;
            den += fabsf(sg);
        }
        float inv = 1.f / den;
        #pragma unroll
        for (int cc = 0; cc < 4; cc++)
            ctr[cc] = sgv[cc] * inv * x1s[cc * 16 + b];
        #pragma unroll
        for (int d = 8; d > 0; d >>= 1) {
            #pragma unroll
            for (int cc = 0; cc < 4; cc++)
                ctr[cc] += __shfl_down_sync(0xffffffffu, ctr[cc], d, 16);
        }
        if (b == 0) {
            #pragma unroll
            for (int cc = 0; cc < 4; cc++) xa2s[cc * 16 + ai] = ctr[cc];
        }
    }
    __syncthreads();

    {
        int o = t >> 3, seg = t & 7;
        float acc = 0.f;
        #pragma unroll
        for (int i = seg * 8; i < seg * 8 + 8; i++)
            acc += W2[o * 64 + i] * xa2s[i];
        #pragma unroll
        for (int d = 4; d > 0; d >>= 1)
            acc += __shfl_down_sync(0xffffffffu, acc, d, 8);
        if (seg == 0) g_X2[n * C2c + o] = acc;
    }

    __threadfence();
    __syncthreads();
    if (t == 0) last = (atomicAdd(&g_cnt2[0], 1) == NN - 1);
    __syncthreads();
    if (!last) return;
    __threadfence();

    float* z = nbs;
    for (int i = t; i < NN * C2c; i += 256) z[i] = g_X2[i];
    __syncthreads();

    {
        int q = t & 31, g = t >> 5;
        float s1 = 0.f, s2 = 0.f;
        #pragma unroll
        for (int nn = g * 8; nn < g * 8 + 8; nn++) {
            float v = z[nn * C2c + q];
            s1 += v; s2 += v * v;
        }
        red[q * 8 + g] = s1; red[256 + q * 8 + g] = s2;
    }
    __syncthreads();
    __shared__ float qm[C2c], qr[C2c];
    if (t < C2c) {
        float s1 = 0.f, s2 = 0.f;
        #pragma unroll
        for (int g = 0; g < 8; g++) { s1 += red[t * 8 + g]; s2 += red[256 + t * 8 + g]; }
        float m = s1 / 64.f;
        qm[t] = m; qr[t] = rsqrtf(s2 / 64.f - m * m + BN_EPS);
    }
    __syncthreads();
    for (int i = t; i < NN * C2c; i += 256) {
        int q = i & 31;
        float y = (z[i] - qm[q]) * qr[q] * bn2w[q] + bn2b[q];
        z[i] = y / (1.f + fabsf(y));
    }
    __syncthreads();
    for (int i = t; i < NN * NCLS; i += 256) {
        int nn = i / NCLS, cls = i - nn * NCLS;
        float acc = lb[cls];
        #pragma unroll
        for (int q = 0; q < C2c; q++) acc += z[nn * C2c + q] * lw[cls * C2c + q];
        out[i] = acc;
    }
}

// ============================================================================
extern "C" void kernel_launch(void* const* d_in, const int* in_sizes, int n_in,
                              void* d_out, int out_size)
{
    const float* x    = (const float*)d_in[0];
    const float* nb   = (const float*)d_in[1];
    const float* W1   = (const float*)d_in[2];
    const float* W2   = (const float*)d_in[3];
    const float* bn1w = (const float*)d_in[4];
    const float* bn1b = (const float*)d_in[5];
    const float* bn2w = (const float*)d_in[6];
    const float* bn2b = (const float*)d_in[7];
    const float* lw   = (const float*)d_in[8];
    const float* lb   = (const float*)d_in[9];
    float* out = (float*)d_out;

    dim3 gp(4, NN);
    k_pre<<<gp, 256>>>(nb);
    k_sort<<<NN, 1024>>>(x);
    dim3 gc(11, NN);
    k_cols<<<gc, 1024>>>(x, nb);
    dim3 gg(33, 8);
    k_gemm<<<gg, 256>>>(W1);
    k_layer2<<<NN, 256>>>(W2, bn1w, bn1b, bn2w, bn2b, lw, lb, out);
}

// round 14
// speedup vs baseline: 1.0185x; 1.0185x over previous
#include <cuda_runtime.h>
#include <math.h>

#define NN   64
#define KK   32
#define FF   1024
#define OO   64
#define JJ   33
#define C2c  32
#define NCLS 10
#define BN_EPS 1e-5f

typedef unsigned long long ull;
typedef unsigned int uint;

// ---------------- scratch ----------------
__device__ float g_C[NN * JJ * FF];
__device__ float g_part[8 * NN * JJ * OO];
__device__ float g_O1[NN * JJ * OO];
__device__ float g_Xrow[NN * OO];
__device__ float g_X2[NN * C2c];
__device__ uint  g_aux[NN * FF];             // packed: ip(10) | m(11)<<10 | neg<<21
__device__ int   g_cnt[64];
__device__ int   g_cnt2[1];

__device__ __forceinline__ ull pk2(float lo, float hi) {
    ull r; asm("mov.b64 %0, {%1, %2};" : "=l"(r) : "f"(lo), "f"(hi)); return r;
}
__device__ __forceinline__ void upk2(ull v, float& lo, float& hi) {
    asm("mov.b64 {%0, %1}, %2;" : "=f"(lo), "=f"(hi) : "l"(v));
}
__device__ __forceinline__ ull ffma2(ull a, ull b, ull c) {
    ull d; asm("fma.rn.f32x2 %0, %1, %2, %3;" : "=l"(d) : "l"(a), "l"(b), "l"(c)); return d;
}

// ============================================================================
// K1: per-node hybrid bitonic sort (payload, float2 smem, double-buffered:
// ONE barrier per cross-warp pass). grid=64, block=1024.  (R12-proven)
// ============================================================================
__global__ void k_sort(const float* __restrict__ x, const float* __restrict__ nb)
{
    int n = blockIdx.x, t = threadIdx.x;
    __shared__ float2 buf[2][FF];            // 16 KB

    if (n == 0 && t < 64) g_cnt[t] = 0;
    if (n == 0 && t == 64) g_cnt2[0] = 0;

    float xv = x[(size_t)n * FF + t];
    const float* nbb = nb + (size_t)n * KK * FF;
    float s = 0.f;
    #pragma unroll
    for (int k = 0; k < KK; k++) s += nbb[k * FF + t];

    float key = s / xv;
    int   pay = t;
    float myr = key;

    #pragma unroll
    for (int k = 2; k <= 32; k <<= 1) {
        #pragma unroll
        for (int j = k >> 1; j >= 1; j >>= 1) {
            float ok = __shfl_xor_sync(0xffffffffu, key, j);
            int   op = __shfl_xor_sync(0xffffffffu, pay, j);
            bool keepmin = (((t & k) == 0) == ((t & j) == 0));
            bool take = keepmin ? (ok < key) : (ok > key);
            if (take) { key = ok; pay = op; }
        }
    }
    int c = 0;
    for (int k = 64; k <= FF; k <<= 1) {
        for (int j = k >> 1; j >= 32; j >>= 1) {
            buf[c][t] = make_float2(key, __int_as_float(pay));
            __syncthreads();
            float2 o = buf[c][t ^ j];
            bool keepmin = (((t & k) == 0) == ((t & j) == 0));
            bool take = keepmin ? (o.x < key) : (o.x > key);
            if (take) { key = o.x; pay = __float_as_int(o.y); }
            c ^= 1;
        }
        #pragma unroll
        for (int j = 16; j >= 1; j >>= 1) {
            float ok = __shfl_xor_sync(0xffffffffu, key, j);
            int   op = __shfl_xor_sync(0xffffffffu, pay, j);
            bool keepmin = (((t & k) == 0) == ((t & j) == 0));
            bool take = keepmin ? (ok < key) : (ok > key);
            if (take) { key = ok; pay = op; }
        }
    }

    __syncthreads();
    float* sk  = (float*)&buf[0][0];
    int*   ipA = (int*)&buf[1][0];
    sk[t] = key;
    ipA[pay] = t;
    __syncthreads();

    float th = -myr;
    int lo = 0, hi = FF;
    #pragma unroll
    for (int it = 0; it < 10; it++) {
        int mid = (lo + hi) >> 1;
        if (sk[mid] < th) lo = mid + 1; else hi = mid;
    }
    uint pk = (uint)ipA[t] | ((uint)lo << 10) | ((xv >= 0.f) ? 0u : (1u << 21));
    g_aux[(size_t)n * FF + t] = pk;
}

// ============================================================================
// K2: batched 6-column scan. grid=(6,64), block=1024.
// Columns >= 33 are clamped duplicates (computed, not stored).
// ============================================================================
__global__ void k_cols(const float* __restrict__ x, const float* __restrict__ nb)
{
    int n = blockIdx.y, t = threadIdx.x;
    int j0 = blockIdx.x * 6;                 // 0,6,12,18,24,30
    __shared__ float sc[6][FF];
    __shared__ float ws[6][32];

    uint  pk = g_aux[(size_t)n * FF + t];
    int   ip = pk & 1023;
    int   m  = (pk >> 10) & 2047;
    float sg = (pk & (1u << 21)) ? -1.f : 1.f;

    float v[6];
    #pragma unroll
    for (int u = 0; u < 6; u++) {
        int j = j0 + u; if (j > 32) j = 32;  // clamp (duplicate work, no store)
        const float* col = (j == 0) ? (x + (size_t)n * FF)
                                    : (nb + ((size_t)n * KK + (j - 1)) * FF);
        v[u] = col[t] * sg;
    }
    #pragma unroll
    for (int u = 0; u < 6; u++) sc[u][ip] = v[u];
    __syncthreads();

    float val[6];
    #pragma unroll
    for (int u = 0; u < 6; u++) val[u] = sc[u][t];

    int lane = t & 31, wid = t >> 5;
    #pragma unroll
    for (int d = 1; d < 32; d <<= 1) {
        #pragma unroll
        for (int u = 0; u < 6; u++) {
            float o = __shfl_up_sync(0xffffffffu, val[u], d);
            if (lane >= d) val[u] += o;
        }
    }
    if (lane == 31) {
        #pragma unroll
        for (int u = 0; u < 6; u++) ws[u][wid] = val[u];
    }
    __syncthreads();
    if (wid == 0) {
        float wv[6];
        #pragma unroll
        for (int u = 0; u < 6; u++) wv[u] = ws[u][lane];
        #pragma unroll
        for (int d = 1; d < 32; d <<= 1) {
            #pragma unroll
            for (int u = 0; u < 6; u++) {
                float o = __shfl_up_sync(0xffffffffu, wv[u], d);
                if (lane >= d) wv[u] += o;
            }
        }
        #pragma unroll
        for (int u = 0; u < 6; u++) ws[u][lane] = wv[u];
    }
    __syncthreads();
    #pragma unroll
    for (int u = 0; u < 6; u++) {
        float off = wid ? ws[u][wid - 1] : 0.f;
        sc[u][t] = val[u] + off;
    }
    __syncthreads();

    #pragma unroll
    for (int u = 0; u < 6; u++) {
        int j = j0 + u;
        if (j < JJ) {
            float T = sc[u][FF - 1];
            float P = m ? sc[u][m - 1] : 0.f;
            g_C[((size_t)n * JJ + j) * FF + t] = sg * (T - 2.f * P);
        }
    }
}

// ============================================================================
// K3: GEMM (split-K 8, FFMA2, DOUBLE-BUFFERED staging) + fused reduce.
// grid=(33,8), block=256.  (R12-proven)
// ============================================================================
__global__ void __launch_bounds__(256) k_gemm(const float* __restrict__ W1)
{
    __shared__ float Cs[2][32 * 68];
    __shared__ float Wt[2][32 * 68];
    __shared__ int last;
    int mt  = blockIdx.x;
    int ks  = blockIdx.y;
    int tid = threadIdx.x;
    int mg  = tid >> 4;
    int og  = tid & 15;

    ull acc01[4], acc23[4];
    #pragma unroll
    for (int i = 0; i < 4; i++) { acc01[i] = pk2(0.f, 0.f); acc23[i] = acc01[i]; }

    int kb0 = ks * (FF / 8);
    int row0 = tid >> 5;
    int kcs  = tid & 31;

    float cv[8], wv[8];
    #pragma unroll
    for (int u = 0; u < 8; u++) {
        int r = row0 + u * 8;
        cv[u] = g_C[(size_t)(mt * 64 + r) * FF + kb0 + kcs];
        wv[u] = W1[(size_t)r * FF + kb0 + kcs];
    }
    #pragma unroll
    for (int u = 0; u < 8; u++) {
        int r = row0 + u * 8;
        Cs[0][kcs * 68 + r] = cv[u];
        Wt[0][kcs * 68 + r] = wv[u];
    }
    __syncthreads();

    int cb = 0;
    #pragma unroll
    for (int blk = 0; blk < 4; blk++) {
        if (blk < 3) {
            int kb = kb0 + (blk + 1) * 32;
            #pragma unroll
            for (int u = 0; u < 8; u++) {
                int r = row0 + u * 8;
                cv[u] = g_C[(size_t)(mt * 64 + r) * FF + kb + kcs];
                wv[u] = W1[(size_t)r * FF + kb + kcs];
            }
        }
        #pragma unroll
        for (int kc = 0; kc < 32; kc++) {
            float4 cvv = *(const float4*)&Cs[cb][kc * 68 + mg * 4];
            ulonglong2 wvv = *(const ulonglong2*)&Wt[cb][kc * 68 + og * 4];
            ull cp;
            cp = pk2(cvv.x, cvv.x);
            acc01[0] = ffma2(cp, wvv.x, acc01[0]); acc23[0] = ffma2(cp, wvv.y, acc23[0]);
            cp = pk2(cvv.y, cvv.y);
            acc01[1] = ffma2(cp, wvv.x, acc01[1]); acc23[1] = ffma2(cp, wvv.y, acc23[1]);
            cp = pk2(cvv.z, cvv.z);
            acc01[2] = ffma2(cp, wvv.x, acc01[2]); acc23[2] = ffma2(cp, wvv.y, acc23[2]);
            cp = pk2(cvv.w, cvv.w);
            acc01[3] = ffma2(cp, wvv.x, acc01[3]); acc23[3] = ffma2(cp, wvv.y, acc23[3]);
        }
        if (blk < 3) {
            #pragma unroll
            for (int u = 0; u < 8; u++) {
                int r = row0 + u * 8;
                Cs[cb ^ 1][kcs * 68 + r] = cv[u];
                Wt[cb ^ 1][kcs * 68 + r] = wv[u];
            }
        }
        __syncthreads();
        cb ^= 1;
    }

    float* pb = g_part + (size_t)ks * (NN * JJ * OO) + (size_t)mt * 64 * OO;
    #pragma unroll
    for (int i = 0; i < 4; i++) {
        float4 r;
        upk2(acc01[i], r.x, r.y);
        upk2(acc23[i], r.z, r.w);
        *(float4*)&pb[(mg * 4 + i) * OO + og * 4] = r;
    }

    __threadfence();
    __syncthreads();
    if (tid == 0) last = (atomicAdd(&g_cnt[mt], 1) == 7);
    __syncthreads();
    if (last) {
        __threadfence();
        const float4* ps = (const float4*)g_part;
        float4* po = (float4*)g_O1;
        float4* px = (float4*)g_Xrow;
        for (int i = tid; i < 1024; i += 256) {
            float4 a = make_float4(0.f, 0.f, 0.f, 0.f);
            #pragma unroll
            for (int s = 0; s < 8; s++) {
                float4 p = ps[(size_t)s * (NN * JJ * OO / 4) + mt * 1024 + i];
                a.x += p.x; a.y += p.y; a.z += p.z; a.w += p.w;
            }
            po[mt * 1024 + i] = a;
            int m = mt * 64 + (i >> 4);
            if (m % 33 == 0) px[(m / 33) * 16 + (i & 15)] = a;
        }
    }
}

// ============================================================================
// K4: layer2 + fused final. grid=64, block=256.  (R10-proven version)
// ============================================================================
__global__ void k_layer2(const float* __restrict__ W2,
                         const float* __restrict__ bn1w, const float* __restrict__ bn1b,
                         const float* __restrict__ bn2w, const float* __restrict__ bn2b,
                         const float* __restrict__ lw,  const float* __restrict__ lb,
                         float* __restrict__ out)
{
    int n = blockIdx.x, t = threadIdx.x;
    __shared__ float nbs[KK * 64];
    __shared__ float red[1024];
    __shared__ float tmp[16];
    __shared__ float x1s[64], t2s[64], xa2s[64];
    __shared__ float gm[4], gr[4], cm[4], cr[4];
    __shared__ int last;

    const float4* O1v = (const float4*)g_O1;
    const float4* Xv  = (const float4*)g_Xrow;
    float4* nbsv = (float4*)nbs;

    #pragma unroll
    for (int u = 0; u < 2; u++) {
        int i4 = u * 256 + t;
        int row = i4 >> 4, c4 = i4 & 15;
        nbsv[i4] = O1v[((size_t)(n * JJ + 1 + row)) * 16 + c4];
    }

    int ch = (t & 15) >> 2;
    float gs1 = 0.f, gs2 = 0.f;
    #pragma unroll
    for (int u = 0; u < 4; u++) {
        float4 q = Xv[u * 256 + t];
        gs1 += q.x + q.y + q.z + q.w;
        gs2 += q.x * q.x + q.y * q.y + q.z * q.z + q.w * q.w;
    }
    __syncthreads();

    float ns1 = 0.f, ns2 = 0.f;
    #pragma unroll
    for (int u = 0; u < 2; u++) {
        float4 q = nbsv[u * 256 + t];
        ns1 += q.x + q.y + q.z + q.w;
        ns2 += q.x * q.x + q.y * q.y + q.z * q.z + q.w * q.w;
    }
    int sic = ((t >> 4) << 2) | (t & 3);
    red[      ch * 64 + sic] = gs1;
    red[256 + ch * 64 + sic] = gs2;
    red[512 + ch * 64 + sic] = ns1;
    red[768 + ch * 64 + sic] = ns2;
    __syncthreads();

    {
        int arr = t >> 6, c = (t >> 4) & 3, l = t & 15;
        int base = arr * 256 + c * 64;
        float v = red[base + l] + red[base + l + 16] + red[base + l + 32] + red[base + l + 48];
        #pragma unroll
        for (int d = 8; d > 0; d >>= 1)
            v += __shfl_down_sync(0xffffffffu, v, d, 16);
        if (l == 0) tmp[arr * 4 + c] = v;
    }
    __syncthreads();
    if (t < 4) {
        float m = tmp[t] / 1024.f;
        gm[t] = m; gr[t] = rsqrtf(tmp[4 + t] / 1024.f - m * m + BN_EPS);
        float m2 = tmp[8 + t] / 512.f;
        cm[t] = m2; cr[t] = rsqrtf(tmp[12 + t] / 512.f - m2 * m2 + BN_EPS);
    }
    __syncthreads();

    if (t < 64) {
        float v = g_Xrow[n * OO + t];
        int c = t >> 4;
        float y = (v - gm[c]) * gr[c] * bn1w[c] + bn1b[c];
        x1s[t] = y / (1.f + fabsf(y));
    }
    #pragma unroll
    for (int u = 0; u < 2; u++) {
        int i4 = u * 256 + t;
        int c = ((i4 & 15) >> 2);
        float4 q = nbsv[i4];
        float sw = cr[c] * bn1w[c];
        float y;
        y = (q.x - cm[c]) * sw + bn1b[c]; q.x = y / (1.f + fabsf(y));
        y = (q.y - cm[c]) * sw + bn1b[c]; q.y = y / (1.f + fabsf(y));
        y = (q.z - cm[c]) * sw + bn1b[c]; q.z = y / (1.f + fabsf(y));
        y = (q.w - cm[c]) * sw + bn1b[c]; q.w = y / (1.f + fabsf(y));
        nbsv[i4] = q;
    }
    __syncthreads();
    if (t < 64) {
        float a = 0.f;
        #pragma unroll
        for (int k = 0; k < KK; k++) a += nbs[k * 64 + t];
        t2s[t] = a;
    }
    __syncthreads();

    {
        int ai = t >> 4, b = t & 15;
        float sgv[4], ctr[4];
        float den = 1e-7f;
        #pragma unroll
        for (int cc = 0; cc < 4; cc++) {
            float raw = x1s[cc * 16 + ai] * t2s[cc * 16 + b]
                      + x1s[cc * 16 + b]  * t2s[cc * 16 + ai];
            float mag = sqrtf(fmaxf(fabsf(raw), 1e-8f));
            float sg  = (raw > 0.f) ? mag : ((raw < 0.f) ? -mag : 0.f);
            sgv[cc] = sg;
            den += fabsf(sg);
        }
        float inv = 1.f / den;
        #pragma unroll
        for (int cc = 0; cc < 4; cc++)
            ctr[cc] = sgv[cc] * inv * x1s[cc * 16 + b];
        #pragma unroll
        for (int d = 8; d > 0; d >>= 1) {
            #pragma unroll
            for (int cc = 0; cc < 4; cc++)
                ctr[cc] += __shfl_down_sync(0xffffffffu, ctr[cc], d, 16);
        }
        if (b == 0) {
            #pragma unroll
            for (int cc = 0; cc < 4; cc++) xa2s[cc * 16 + ai] = ctr[cc];
        }
    }
    __syncthreads();

    {
        int o = t >> 3, seg = t & 7;
        float acc = 0.f;
        #pragma unroll
        for (int i = seg * 8; i < seg * 8 + 8; i++)
            acc += W2[o * 64 + i] * xa2s[i];
        #pragma unroll
        for (int d = 4; d > 0; d >>= 1)
            acc += __shfl_down_sync(0xffffffffu, acc, d, 8);
        if (seg == 0) g_X2[n * C2c + o] = acc;
    }

    __threadfence();
    __syncthreads();
    if (t == 0) last = (atomicAdd(&g_cnt2[0], 1) == NN - 1);
    __syncthreads();
    if (!last) return;
    __threadfence();

    float* z = nbs;
    for (int i = t; i < NN * C2c; i += 256) z[i] = g_X2[i];
    __syncthreads();

    {
        int q = t & 31, g = t >> 5;
        float s1 = 0.f, s2 = 0.f;
        #pragma unroll
        for (int nn = g * 8; nn < g * 8 + 8; nn++) {
            float v = z[nn * C2c + q];
            s1 += v; s2 += v * v;
        }
        red[q * 8 + g] = s1; red[256 + q * 8 + g] = s2;
    }
    __syncthreads();
    __shared__ float qm[C2c], qr[C2c];
    if (t < C2c) {
        float s1 = 0.f, s2 = 0.f;
        #pragma unroll
        for (int g = 0; g < 8; g++) { s1 += red[t * 8 + g]; s2 += red[256 + t * 8 + g]; }
        float m = s1 / 64.f;
        qm[t] = m; qr[t] = rsqrtf(s2 / 64.f - m * m + BN_EPS);
    }
    __syncthreads();
    for (int i = t; i < NN * C2c; i += 256) {
        int q = i & 31;
        float y = (z[i] - qm[q]) * qr[q] * bn2w[q] + bn2b[q];
        z[i] = y / (1.f + fabsf(y));
    }
    __syncthreads();
    for (int i = t; i < NN * NCLS; i += 256) {
        int nn = i / NCLS, cls = i - nn * NCLS;
        float acc = lb[cls];
        #pragma unroll
        for (int q = 0; q < C2c; q++) acc += z[nn * C2c + q] * lw[cls * C2c + q];
        out[i] = acc;
    }
}

// ============================================================================
extern "C" void kernel_launch(void* const* d_in, const int* in_sizes, int n_in,
                              void* d_out, int out_size)
{
    const float* x    = (const float*)d_in[0];
    const float* nb   = (const float*)d_in[1];
    const float* W1   = (const float*)d_in[2];
    const float* W2   = (const float*)d_in[3];
    const float* bn1w = (const float*)d_in[4];
    const float* bn1b = (const float*)d_in[5];
    const float* bn2w = (const float*)d_in[6];
    const float* bn2b = (const float*)d_in[7];
    const float* lw   = (const float*)d_in[8];
    const float* lb   = (const float*)d_in[9];
    float* out = (float*)d_out;

    k_sort<<<NN, 1024>>>(x, nb);
    dim3 gc(6, NN);
    k_cols<<<gc, 1024>>>(x, nb);
    dim3 gg(33, 8);
    k_gemm<<<gg, 256>>>(W1);
    k_layer2<<<NN, 256>>>(W2, bn1w, bn1b, bn2w, bn2b, lw, lb, out);
}

// round 15
// speedup vs baseline: 1.0468x; 1.0278x over previous
#include <cuda_runtime.h>
#include <math.h>

#define NN   64
#define KK   32
#define FF   1024
#define OO   64
#define JJ   33
#define C2c  32
#define NCLS 10
#define BN_EPS 1e-5f

typedef unsigned long long ull;
typedef unsigned int uint;

// ---------------- scratch ----------------
__device__ float g_C[NN * JJ * FF];
__device__ float g_part[8 * NN * JJ * OO];
__device__ float g_O1[NN * JJ * OO];
__device__ float g_Xrow[NN * OO];
__device__ float g_X2[NN * C2c];
__device__ uint  g_aux[NN * FF];             // packed: ip(10) | m(11)<<10 | neg<<21
__device__ int   g_cnt[64];
__device__ int   g_cnt2[1];

__device__ __forceinline__ ull pk2(float lo, float hi) {
    ull r; asm("mov.b64 %0, {%1, %2};" : "=l"(r) : "f"(lo), "f"(hi)); return r;
}
__device__ __forceinline__ void upk2(ull v, float& lo, float& hi) {
    asm("mov.b64 {%0, %1}, %2;" : "=f"(lo), "=f"(hi) : "l"(v));
}
__device__ __forceinline__ ull ffma2(ull a, ull b, ull c) {
    ull d; asm("fma.rn.f32x2 %0, %1, %2, %3;" : "=l"(d) : "l"(a), "l"(b), "l"(c)); return d;
}

// ============================================================================
// K1: per-node hybrid bitonic sort (payload, float2 smem, double-buffered:
// ONE barrier per cross-warp pass). grid=64, block=1024.  (R12-proven)
// ============================================================================
__global__ void k_sort(const float* __restrict__ x, const float* __restrict__ nb)
{
    int n = blockIdx.x, t = threadIdx.x;
    __shared__ float2 buf[2][FF];            // 16 KB

    if (n == 0 && t < 64) g_cnt[t] = 0;
    if (n == 0 && t == 64) g_cnt2[0] = 0;

    float xv = x[(size_t)n * FF + t];
    const float* nbb = nb + (size_t)n * KK * FF;
    float s = 0.f;
    #pragma unroll
    for (int k = 0; k < KK; k++) s += nbb[k * FF + t];

    float key = s / xv;
    int   pay = t;
    float myr = key;

    #pragma unroll
    for (int k = 2; k <= 32; k <<= 1) {
        #pragma unroll
        for (int j = k >> 1; j >= 1; j >>= 1) {
            float ok = __shfl_xor_sync(0xffffffffu, key, j);
            int   op = __shfl_xor_sync(0xffffffffu, pay, j);
            bool keepmin = (((t & k) == 0) == ((t & j) == 0));
            bool take = keepmin ? (ok < key) : (ok > key);
            if (take) { key = ok; pay = op; }
        }
    }
    int c = 0;
    for (int k = 64; k <= FF; k <<= 1) {
        for (int j = k >> 1; j >= 32; j >>= 1) {
            buf[c][t] = make_float2(key, __int_as_float(pay));
            __syncthreads();
            float2 o = buf[c][t ^ j];
            bool keepmin = (((t & k) == 0) == ((t & j) == 0));
            bool take = keepmin ? (o.x < key) : (o.x > key);
            if (take) { key = o.x; pay = __float_as_int(o.y); }
            c ^= 1;
        }
        #pragma unroll
        for (int j = 16; j >= 1; j >>= 1) {
            float ok = __shfl_xor_sync(0xffffffffu, key, j);
            int   op = __shfl_xor_sync(0xffffffffu, pay, j);
            bool keepmin = (((t & k) == 0) == ((t & j) == 0));
            bool take = keepmin ? (ok < key) : (ok > key);
            if (take) { key = ok; pay = op; }
        }
    }

    __syncthreads();
    float* sk  = (float*)&buf[0][0];
    int*   ipA = (int*)&buf[1][0];
    sk[t] = key;
    ipA[pay] = t;
    __syncthreads();

    float th = -myr;
    int lo = 0, hi = FF;
    #pragma unroll
    for (int it = 0; it < 10; it++) {
        int mid = (lo + hi) >> 1;
        if (sk[mid] < th) lo = mid + 1; else hi = mid;
    }
    uint pk = (uint)ipA[t] | ((uint)lo << 10) | ((xv >= 0.f) ? 0u : (1u << 21));
    g_aux[(size_t)n * FF + t] = pk;
}

// ============================================================================
// K2: batched 3-column scan with PDL. grid=(11,64), block=1024.
// Column loads (x/nb) are hoisted above the grid-dependency sync.
// ============================================================================
__global__ void k_cols(const float* __restrict__ x, const float* __restrict__ nb)
{
    int n = blockIdx.y, t = threadIdx.x;
    int j0 = blockIdx.x * 3;
    __shared__ float sc[3][FF];
    __shared__ float ws[3][32];

    // independent prologue: raw column loads (no dependence on k_sort)
    float vr[3];
    #pragma unroll
    for (int u = 0; u < 3; u++) {
        int j = j0 + u;
        const float* col = (j == 0) ? (x + (size_t)n * FF)
                                    : (nb + ((size_t)n * KK + (j - 1)) * FF);
        vr[u] = col[t];
    }

    cudaGridDependencySynchronize();         // wait for k_sort's g_aux

    uint  pk = g_aux[(size_t)n * FF + t];
    int   ip = pk & 1023;
    int   m  = (pk >> 10) & 2047;
    float sg = (pk & (1u << 21)) ? -1.f : 1.f;

    #pragma unroll
    for (int u = 0; u < 3; u++) sc[u][ip] = vr[u] * sg;
    __syncthreads();

    float val[3];
    #pragma unroll
    for (int u = 0; u < 3; u++) val[u] = sc[u][t];

    int lane = t & 31, wid = t >> 5;
    #pragma unroll
    for (int d = 1; d < 32; d <<= 1) {
        #pragma unroll
        for (int u = 0; u < 3; u++) {
            float o = __shfl_up_sync(0xffffffffu, val[u], d);
            if (lane >= d) val[u] += o;
        }
    }
    if (lane == 31) {
        #pragma unroll
        for (int u = 0; u < 3; u++) ws[u][wid] = val[u];
    }
    __syncthreads();
    if (wid == 0) {
        float wv[3];
        #pragma unroll
        for (int u = 0; u < 3; u++) wv[u] = ws[u][lane];
        #pragma unroll
        for (int d = 1; d < 32; d <<= 1) {
            #pragma unroll
            for (int u = 0; u < 3; u++) {
                float o = __shfl_up_sync(0xffffffffu, wv[u], d);
                if (lane >= d) wv[u] += o;
            }
        }
        #pragma unroll
        for (int u = 0; u < 3; u++) ws[u][lane] = wv[u];
    }
    __syncthreads();
    #pragma unroll
    for (int u = 0; u < 3; u++) {
        float off = wid ? ws[u][wid - 1] : 0.f;
        sc[u][t] = val[u] + off;
    }
    __syncthreads();

    #pragma unroll
    for (int u = 0; u < 3; u++) {
        float T = sc[u][FF - 1];
        float P = m ? sc[u][m - 1] : 0.f;
        g_C[((size_t)n * JJ + j0 + u) * FF + t] = sg * (T - 2.f * P);
    }
}

// ============================================================================
// K3: GEMM (split-K 8, FFMA2, double-buffered) + fused reduce, PDL.
// W1 first-tile load hoisted above the dependency sync. grid=(33,8), block=256.
// ============================================================================
__global__ void __launch_bounds__(256) k_gemm(const float* __restrict__ W1)
{
    __shared__ float Cs[2][32 * 68];
    __shared__ float Wt[2][32 * 68];
    __shared__ int last;
    int mt  = blockIdx.x;
    int ks  = blockIdx.y;
    int tid = threadIdx.x;
    int mg  = tid >> 4;
    int og  = tid & 15;

    ull acc01[4], acc23[4];
    #pragma unroll
    for (int i = 0; i < 4; i++) { acc01[i] = pk2(0.f, 0.f); acc23[i] = acc01[i]; }

    int kb0 = ks * (FF / 8);
    int row0 = tid >> 5;
    int kcs  = tid & 31;

    // independent prologue: W1 first tile (no dependence on k_cols)
    float cv[8], wv[8];
    #pragma unroll
    for (int u = 0; u < 8; u++) {
        int r = row0 + u * 8;
        wv[u] = W1[(size_t)r * FF + kb0 + kcs];
    }

    cudaGridDependencySynchronize();         // wait for k_cols' g_C

    #pragma unroll
    for (int u = 0; u < 8; u++) {
        int r = row0 + u * 8;
        cv[u] = g_C[(size_t)(mt * 64 + r) * FF + kb0 + kcs];
    }
    #pragma unroll
    for (int u = 0; u < 8; u++) {
        int r = row0 + u * 8;
        Cs[0][kcs * 68 + r] = cv[u];
        Wt[0][kcs * 68 + r] = wv[u];
    }
    __syncthreads();

    int cb = 0;
    #pragma unroll
    for (int blk = 0; blk < 4; blk++) {
        if (blk < 3) {
            int kb = kb0 + (blk + 1) * 32;
            #pragma unroll
            for (int u = 0; u < 8; u++) {
                int r = row0 + u * 8;
                cv[u] = g_C[(size_t)(mt * 64 + r) * FF + kb + kcs];
                wv[u] = W1[(size_t)r * FF + kb + kcs];
            }
        }
        #pragma unroll
        for (int kc = 0; kc < 32; kc++) {
            float4 cvv = *(const float4*)&Cs[cb][kc * 68 + mg * 4];
            ulonglong2 wvv = *(const ulonglong2*)&Wt[cb][kc * 68 + og * 4];
            ull cp;
            cp = pk2(cvv.x, cvv.x);
            acc01[0] = ffma2(cp, wvv.x, acc01[0]); acc23[0] = ffma2(cp, wvv.y, acc23[0]);
            cp = pk2(cvv.y, cvv.y);
            acc01[1] = ffma2(cp, wvv.x, acc01[1]); acc23[1] = ffma2(cp, wvv.y, acc23[1]);
            cp = pk2(cvv.z, cvv.z);
            acc01[2] = ffma2(cp, wvv.x, acc01[2]); acc23[2] = ffma2(cp, wvv.y, acc23[2]);
            cp = pk2(cvv.w, cvv.w);
            acc01[3] = ffma2(cp, wvv.x, acc01[3]); acc23[3] = ffma2(cp, wvv.y, acc23[3]);
        }
        if (blk < 3) {
            #pragma unroll
            for (int u = 0; u < 8; u++) {
                int r = row0 + u * 8;
                Cs[cb ^ 1][kcs * 68 + r] = cv[u];
                Wt[cb ^ 1][kcs * 68 + r] = wv[u];
            }
        }
        __syncthreads();
        cb ^= 1;
    }

    float* pb = g_part + (size_t)ks * (NN * JJ * OO) + (size_t)mt * 64 * OO;
    #pragma unroll
    for (int i = 0; i < 4; i++) {
        float4 r;
        upk2(acc01[i], r.x, r.y);
        upk2(acc23[i], r.z, r.w);
        *(float4*)&pb[(mg * 4 + i) * OO + og * 4] = r;
    }

    __threadfence();
    __syncthreads();
    if (tid == 0) last = (atomicAdd(&g_cnt[mt], 1) == 7);
    __syncthreads();
    if (last) {
        __threadfence();
        const float4* ps = (const float4*)g_part;
        float4* po = (float4*)g_O1;
        float4* px = (float4*)g_Xrow;
        for (int i = tid; i < 1024; i += 256) {
            float4 a = make_float4(0.f, 0.f, 0.f, 0.f);
            #pragma unroll
            for (int s = 0; s < 8; s++) {
                float4 p = ps[(size_t)s * (NN * JJ * OO / 4) + mt * 1024 + i];
                a.x += p.x; a.y += p.y; a.z += p.z; a.w += p.w;
            }
            po[mt * 1024 + i] = a;
            int m = mt * 64 + (i >> 4);
            if (m % 33 == 0) px[(m / 33) * 16 + (i & 15)] = a;
        }
    }
}

// ============================================================================
// K4: layer2 + fused final, PDL. grid=64, block=256.
// ============================================================================
__global__ void k_layer2(const float* __restrict__ W2,
                         const float* __restrict__ bn1w, const float* __restrict__ bn1b,
                         const float* __restrict__ bn2w, const float* __restrict__ bn2b,
                         const float* __restrict__ lw,  const float* __restrict__ lb,
                         float* __restrict__ out)
{
    int n = blockIdx.x, t = threadIdx.x;
    __shared__ float nbs[KK * 64];
    __shared__ float red[1024];
    __shared__ float tmp[16];
    __shared__ float x1s[64], t2s[64], xa2s[64];
    __shared__ float gm[4], gr[4], cm[4], cr[4];
    __shared__ int last;

    // independent prologue: bn1 params into registers
    float b1w = bn1w[t & 3], b1b = bn1b[t & 3];
    (void)b1w; (void)b1b;

    cudaGridDependencySynchronize();         // wait for k_gemm's g_O1/g_Xrow

    const float4* O1v = (const float4*)g_O1;
    const float4* Xv  = (const float4*)g_Xrow;
    float4* nbsv = (float4*)nbs;

    #pragma unroll
    for (int u = 0; u < 2; u++) {
        int i4 = u * 256 + t;
        int row = i4 >> 4, c4 = i4 & 15;
        nbsv[i4] = O1v[((size_t)(n * JJ + 1 + row)) * 16 + c4];
    }

    int ch = (t & 15) >> 2;
    float gs1 = 0.f, gs2 = 0.f;
    #pragma unroll
    for (int u = 0; u < 4; u++) {
        float4 q = Xv[u * 256 + t];
        gs1 += q.x + q.y + q.z + q.w;
        gs2 += q.x * q.x + q.y * q.y + q.z * q.z + q.w * q.w;
    }
    __syncthreads();

    float ns1 = 0.f, ns2 = 0.f;
    #pragma unroll
    for (int u = 0; u < 2; u++) {
        float4 q = nbsv[u * 256 + t];
        ns1 += q.x + q.y + q.z + q.w;
        ns2 += q.x * q.x + q.y * q.y + q.z * q.z + q.w * q.w;
    }
    int sic = ((t >> 4) << 2) | (t & 3);
    red[      ch * 64 + sic] = gs1;
    red[256 + ch * 64 + sic] = gs2;
    red[512 + ch * 64 + sic] = ns1;
    red[768 + ch * 64 + sic] = ns2;
    __syncthreads();

    {
        int arr = t >> 6, c = (t >> 4) & 3, l = t & 15;
        int base = arr * 256 + c * 64;
        float v = red[base + l] + red[base + l + 16] + red[base + l + 32] + red[base + l + 48];
        #pragma unroll
        for (int d = 8; d > 0; d >>= 1)
            v += __shfl_down_sync(0xffffffffu, v, d, 16);
        if (l == 0) tmp[arr * 4 + c] = v;
    }
    __syncthreads();
    if (t < 4) {
        float m = tmp[t] / 1024.f;
        gm[t] = m; gr[t] = rsqrtf(tmp[4 + t] / 1024.f - m * m + BN_EPS);
        float m2 = tmp[8 + t] / 512.f;
        cm[t] = m2; cr[t] = rsqrtf(tmp[12 + t] / 512.f - m2 * m2 + BN_EPS);
    }
    __syncthreads();

    if (t < 64) {
        float v = g_Xrow[n * OO + t];
        int c = t >> 4;
        float y = (v - gm[c]) * gr[c] * bn1w[c] + bn1b[c];
        x1s[t] = y / (1.f + fabsf(y));
    }
    #pragma unroll
    for (int u = 0; u < 2; u++) {
        int i4 = u * 256 + t;
        int c = ((i4 & 15) >> 2);
        float4 q = nbsv[i4];
        float sw = cr[c] * bn1w[c];
        float y;
        y = (q.x - cm[c]) * sw + bn1b[c]; q.x = y / (1.f + fabsf(y));
        y = (q.y - cm[c]) * sw + bn1b[c]; q.y = y / (1.f + fabsf(y));
        y = (q.z - cm[c]) * sw + bn1b[c]; q.z = y / (1.f + fabsf(y));
        y = (q.w - cm[c]) * sw + bn1b[c]; q.w = y / (1.f + fabsf(y));
        nbsv[i4] = q;
    }
    __syncthreads();
    if (t < 64) {
        float a = 0.f;
        #pragma unroll
        for (int k = 0; k < KK; k++) a += nbs[k * 64 + t];
        t2s[t] = a;
    }
    __syncthreads();

    {
        int ai = t >> 4, b = t & 15;
        float sgv[4], ctr[4];
        float den = 1e-7f;
        #pragma unroll
        for (int cc = 0; cc < 4; cc++) {
            float raw = x1s[cc * 16 + ai] * t2s[cc * 16 + b]
                      + x1s[cc * 16 + b]  * t2s[cc * 16 + ai];
            float mag = sqrtf(fmaxf(fabsf(raw), 1e-8f));
            float sg  = (raw > 0.f) ? mag : ((raw < 0.f) ? -mag : 0.f);
            sgv[cc] = sg;
            den += fabsf(sg);
        }
        float inv = 1.f / den;
        #pragma unroll
        for (int cc = 0; cc < 4; cc++)
            ctr[cc] = sgv[cc] * inv * x1s[cc * 16 + b];
        #pragma unroll
        for (int d = 8; d > 0; d >>= 1) {
            #pragma unroll
            for (int cc = 0; cc < 4; cc++)
                ctr[cc] += __shfl_down_sync(0xffffffffu, ctr[cc], d, 16);
        }
        if (b == 0) {
            #pragma unroll
            for (int cc = 0; cc < 4; cc++) xa2s[cc * 16 + ai] = ctr[cc];
        }
    }
    __syncthreads();

    {
        int o = t >> 3, seg = t & 7;
        float acc = 0.f;
        #pragma unroll
        for (int i = seg * 8; i < seg * 8 + 8; i++)
            acc += W2[o * 64 + i] * xa2s[i];
        #pragma unroll
        for (int d = 4; d > 0; d >>= 1)
            acc += __shfl_down_sync(0xffffffffu, acc, d, 8);
        if (seg == 0) g_X2[n * C2c + o] = acc;
    }

    __threadfence();
    __syncthreads();
    if (t == 0) last = (atomicAdd(&g_cnt2[0], 1) == NN - 1);
    __syncthreads();
    if (!last) return;
    __threadfence();

    float* z = nbs;
    for (int i = t; i < NN * C2c; i += 256) z[i] = g_X2[i];
    __syncthreads();

    {
        int q = t & 31, g = t >> 5;
        float s1 = 0.f, s2 = 0.f;
        #pragma unroll
        for (int nn = g * 8; nn < g * 8 + 8; nn++) {
            float v = z[nn * C2c + q];
            s1 += v; s2 += v * v;
        }
        red[q * 8 + g] = s1; red[256 + q * 8 + g] = s2;
    }
    __syncthreads();
    __shared__ float qm[C2c], qr[C2c];
    if (t < C2c) {
        float s1 = 0.f, s2 = 0.f;
        #pragma unroll
        for (int g = 0; g < 8; g++) { s1 += red[t * 8 + g]; s2 += red[256 + t * 8 + g]; }
        float m = s1 / 64.f;
        qm[t] = m; qr[t] = rsqrtf(s2 / 64.f - m * m + BN_EPS);
    }
    __syncthreads();
    for (int i = t; i < NN * C2c; i += 256) {
        int q = i & 31;
        float y = (z[i] - qm[q]) * qr[q] * bn2w[q] + bn2b[q];
        z[i] = y / (1.f + fabsf(y));
    }
    __syncthreads();
    for (int i = t; i < NN * NCLS; i += 256) {
        int nn = i / NCLS, cls = i - nn * NCLS;
        float acc = lb[cls];
        #pragma unroll
        for (int q = 0; q < C2c; q++) acc += z[nn * C2c + q] * lw[cls * C2c + q];
        out[i] = acc;
    }
}

// ============================================================================
extern "C" void kernel_launch(void* const* d_in, const int* in_sizes, int n_in,
                              void* d_out, int out_size)
{
    const float* x    = (const float*)d_in[0];
    const float* nb   = (const float*)d_in[1];
    const float* W1   = (const float*)d_in[2];
    const float* W2   = (const float*)d_in[3];
    const float* bn1w = (const float*)d_in[4];
    const float* bn1b = (const float*)d_in[5];
    const float* bn2w = (const float*)d_in[6];
    const float* bn2b = (const float*)d_in[7];
    const float* lw   = (const float*)d_in[8];
    const float* lb   = (const float*)d_in[9];
    float* out = (float*)d_out;

    k_sort<<<NN, 1024>>>(x, nb);

    cudaLaunchAttribute attr[1];
    attr[0].id = cudaLaunchAttributeProgrammaticStreamSerialization;
    attr[0].val.programmaticStreamSerializationAllowed = 1;

    {
        cudaLaunchConfig_t cfg = {};
        cfg.gridDim = dim3(11, NN);
        cfg.blockDim = dim3(1024);
        cfg.attrs = attr;
        cfg.numAttrs = 1;
        cudaLaunchKernelEx(&cfg, k_cols, x, nb);
    }
    {
        cudaLaunchConfig_t cfg = {};
        cfg.gridDim = dim3(33, 8);
        cfg.blockDim = dim3(256);
        cfg.attrs = attr;
        cfg.numAttrs = 1;
        cudaLaunchKernelEx(&cfg, k_gemm, W1);
    }
    {
        cudaLaunchConfig_t cfg = {};
        cfg.gridDim = dim3(NN);
        cfg.blockDim = dim3(256);
        cfg.attrs = attr;
        cfg.numAttrs = 1;
        cudaLaunchKernelEx(&cfg, k_layer2, W2, bn1w, bn1b, bn2w, bn2b, lw, lb, out);
    }
}